// round 9
// baseline (speedup 1.0000x reference)
#include <cuda_runtime.h>
#include <math.h>
#include <stdint.h>

#define BS2   2
#define NN    8192
#define NPT   128
#define CC    128
#define M_TOT 8192        // NPT*64 per batch
#define MG    16384       // total corners

// ---------------- device scratch ----------------
static __device__ float g_p2[(size_t)BS2*NN];
static __device__ float g_rel[(size_t)MG*3];
static __device__ float g_cor[(size_t)MG*3];
static __device__ int   g_nni[(size_t)MG*3];
static __device__ float g_nnw[(size_t)MG*3];
static __device__ float g_w1T[128*128];                 // [k][o]
static __device__ float g_w2T[128*256];                 // [k][o]
static __device__ float g_G[(size_t)BS2*NN*128];        // [b][n][o] = W1f . f
static __device__ float g_h1T[(size_t)128*MG];          // [c][m]
static __device__ float g_pool[(size_t)BS2*256*NPT];    // [b][o][p]
static __device__ float g_z0[(size_t)BS2*128*NPT];
static __device__ float g_z1[(size_t)BS2*128*NPT];

__device__ __forceinline__ float tf32r(float x) {
    uint32_t u; asm("cvt.rna.tf32.f32 %0, %1;" : "=r"(u) : "f"(x));
    return __uint_as_float(u);
}

__device__ __forceinline__ void mma_tf32(float c[4], const uint32_t a[4], const uint32_t b[2]) {
    asm volatile(
        "mma.sync.aligned.m16n8k8.row.col.f32.tf32.tf32.f32 "
        "{%0,%1,%2,%3}, {%4,%5,%6,%7}, {%8,%9}, {%0,%1,%2,%3};\n"
        : "+f"(c[0]), "+f"(c[1]), "+f"(c[2]), "+f"(c[3])
        : "r"(a[0]), "r"(a[1]), "r"(a[2]), "r"(a[3]), "r"(b[0]), "r"(b[1]));
}

// ---------------- setup_a: decode + p2 ----------------
__global__ void setup_a_kernel(const float* __restrict__ cand,
                               const float* __restrict__ off,
                               const float* __restrict__ acls,
                               const float* __restrict__ ares,
                               const float* __restrict__ oxyz)
{
    int bx = blockIdx.x, tid = threadIdx.x;
    if (bx < 64) {
        int t = bx*256 + tid;                        // 16384 = b*8192 + p*64 + k
        int k  = t & 63;
        int bp = t >> 6;
        const float* a = acls + bp*12;
        float best = a[0]; int bi = 0;
        #pragma unroll
        for (int j = 1; j < 12; j++) { float v = a[j]; if (v > best) { best = v; bi = j; } }
        float res = ares[bp*12 + bi];
        const float PI_F = 3.14159265358979323846f;
        float ang = (float)bi * (float)(2.0*3.14159265358979323846/12.0) + res;
        float heading = (ang > PI_F) ? (ang - 2.0f*PI_F) : ang;
        float s, c; sincosf(heading, &s, &c);
        const float* o6 = off + bp*6;
        float cx = cand[bp*3+0] + o6[0];
        float cy = cand[bp*3+1] + o6[1];
        float cz = cand[bp*3+2] + o6[2];
        float lx = fmaxf(o6[3]*2.0f, 0.1f);
        float ly = fmaxf(o6[4]*2.0f, 0.1f);
        float lz = fmaxf(o6[5]*2.0f, 0.1f);
        float gv[4] = {-1.0f, -1.0f/3.0f, 1.0f/3.0f, 1.0f};
        float gx = gv[(k>>4)&3] * lx;
        float gy = gv[(k>>2)&3] * ly;
        float gz = gv[k&3]      * lz;
        float rx = gx*c - gy*s;
        float ry = gx*s + gy*c;
        float rz = gz;
        size_t b3 = (size_t)t*3;
        g_rel[b3+0] = rx; g_rel[b3+1] = ry; g_rel[b3+2] = rz;
        g_cor[b3+0] = rx + cx; g_cor[b3+1] = ry + cy; g_cor[b3+2] = rz + cz;
    } else {
        int t = (bx-64)*256 + tid;
        float x = oxyz[t*3], y = oxyz[t*3+1], z = oxyz[t*3+2];
        g_p2[t] = x*x + y*y + z*z;
    }
}

// ---------------- setup_b: transpose W1f / W2 ----------------
__global__ void setup_b_kernel(const float* __restrict__ w1, const float* __restrict__ w2)
{
    int bx = blockIdx.x, tid = threadIdx.x;
    if (bx < 64) {
        int t = bx*256 + tid;                        // 16384 = k*128+o
        int o = t & 127, k = t >> 7;
        g_w1T[t] = w1[o*131 + 3 + k];
    } else {
        int t = (bx-64)*256 + tid;                   // 32768 = k*256+o
        int o = t & 255, k = t >> 8;
        g_w2T[t] = w2[o*128 + k];
    }
}

// ---------------- gemm_G: 128n x 64o, BK=16, 8x4, double-buffered (proven) ----------------
__global__ void __launch_bounds__(256) gemmG_kernel(const float* __restrict__ feat)
{
    __shared__ float Ns[2][16][132];
    __shared__ float Os[2][16][64];
    int n0 = blockIdx.x*128, o0 = blockIdx.y*64, b = blockIdx.z;
    int tid = threadIdx.x;
    int kr  = tid >> 4;
    int nc  = (tid & 15)*8;
    int oc  = (tid & 15)*4;
    int tr  = (tid >> 4)*8;
    int tc  = (tid & 15)*4;
    const float* F = feat + (size_t)b*CC*NN;

    float acc[8][4] = {};
    float4 na0, na1, nb;
    na0 = *(const float4*)&F[(size_t)kr*NN + n0 + nc];
    na1 = *(const float4*)&F[(size_t)kr*NN + n0 + nc + 4];
    nb  = *(const float4*)&g_w1T[kr*128 + o0 + oc];
    *(float4*)&Ns[0][kr][nc]   = na0;
    *(float4*)&Ns[0][kr][nc+4] = na1;
    *(float4*)&Os[0][kr][oc]   = nb;
    __syncthreads();
    int buf = 0;
    #pragma unroll 1
    for (int kb = 0; kb < 8; kb++) {
        bool has = kb < 7;
        if (has) {
            int kk = (kb+1)*16 + kr;
            na0 = *(const float4*)&F[(size_t)kk*NN + n0 + nc];
            na1 = *(const float4*)&F[(size_t)kk*NN + n0 + nc + 4];
            nb  = *(const float4*)&g_w1T[kk*128 + o0 + oc];
        }
        #pragma unroll
        for (int k = 0; k < 16; k++) {
            float4 a0 = *(const float4*)&Ns[buf][k][tr];
            float4 a1 = *(const float4*)&Ns[buf][k][tr+4];
            float4 bq = *(const float4*)&Os[buf][k][tc];
            float ar[8] = {a0.x,a0.y,a0.z,a0.w,a1.x,a1.y,a1.z,a1.w};
            float br[4] = {bq.x,bq.y,bq.z,bq.w};
            #pragma unroll
            for (int i = 0; i < 8; i++)
                #pragma unroll
                for (int j = 0; j < 4; j++)
                    acc[i][j] = fmaf(ar[i], br[j], acc[i][j]);
        }
        if (has) {
            int nbuf = buf^1;
            *(float4*)&Ns[nbuf][kr][nc]   = na0;
            *(float4*)&Ns[nbuf][kr][nc+4] = na1;
            *(float4*)&Os[nbuf][kr][oc]   = nb;
            __syncthreads();
            buf = nbuf;
        }
    }
    float* Gp = g_G + ((size_t)b*NN + n0 + tr)*128 + o0 + tc;
    #pragma unroll
    for (int i = 0; i < 8; i++) {
        float4 v = {acc[i][0], acc[i][1], acc[i][2], acc[i][3]};
        *(float4*)(Gp + (size_t)i*128) = v;
    }
}

// ---------------- top-3 merge helper (reloads center from g_cor) ----------------
__device__ __forceinline__ void merge_write(float d0, float d1, float d2,
                                            int i0, int i1, int i2,
                                            volatile float* mw, volatile int* mi,
                                            int lane, const float* __restrict__ O,
                                            int b, int m)
{
    mw[lane*3+0] = d0; mi[lane*3+0] = i0;
    mw[lane*3+1] = d1; mi[lane*3+1] = i1;
    mw[lane*3+2] = d2; mi[lane*3+2] = i2;
    __syncwarp();
    int win[3];
    #pragma unroll
    for (int r = 0; r < 3; r++) {
        float v = 1e30f; int pos = 1<<30;
        #pragma unroll
        for (int j = 0; j < 3; j++) {
            int jj = lane + 32*j;
            float vv = mw[jj];
            if (vv < v || (vv == v && jj < pos)) { v = vv; pos = jj; }
        }
        #pragma unroll
        for (int offi = 16; offi; offi >>= 1) {
            float v2 = __shfl_xor_sync(0xffffffffu, v, offi);
            int   q2 = __shfl_xor_sync(0xffffffffu, pos, offi);
            if (v2 < v || (v2 == v && q2 < pos)) { v = v2; pos = q2; }
        }
        win[r] = mi[pos];
        if (lane == 0) mw[pos] = 2e30f;
        __syncwarp();
    }
    if (lane == 0) {
        size_t cb = ((size_t)b*M_TOT + m)*3;
        float cx = g_cor[cb+0], cy = g_cor[cb+1], cz = g_cor[cb+2];
        float w[3], ssum = 0.0f;
        #pragma unroll
        for (int r = 0; r < 3; r++) {
            const float* P = O + (size_t)win[r]*3;
            float dx = P[0]-cx, dy = P[1]-cy, dz = P[2]-cz;
            float d = sqrtf(dx*dx + dy*dy + dz*dz);
            w[r] = 1.0f / (d + 1e-8f);
            ssum += w[r];
        }
        size_t base = cb;
        float inv = 1.0f/ssum;
        #pragma unroll
        for (int r = 0; r < 3; r++) { g_nni[base+r] = win[r]; g_nnw[base+r] = w[r]*inv; }
    }
    __syncwarp();
}

// ---------------- three_nn: warp handles 4 corners, fully scalarized ----------------
__global__ void three_nn_kernel(const float* __restrict__ oxyz)
{
    __shared__ float4 st[512];
    __shared__ float  mw[8][96];
    __shared__ int    mi[8][96];
    int tid = threadIdx.x, lane = tid & 31, wid = tid >> 5;
    int gw = blockIdx.x*8 + wid;                     // 0..4095
    int b  = gw >> 11;                               // 2048 warps per batch
    int m0 = (gw & 2047) * 4;
    const float* O = oxyz + (size_t)b*NN*3;
    const float* Q = g_p2 + (size_t)b*NN;

    size_t cb = ((size_t)b*M_TOT + m0)*3;
    float c2A, axA, ayA, azA, c2B, axB, ayB, azB;
    float c2C, axC, ayC, azC, c2D, axD, ayD, azD;
    {
        float x, y, z;
        x = g_cor[cb+0];  y = g_cor[cb+1];  z = g_cor[cb+2];
        c2A = x*x+y*y+z*z; axA = -2.0f*x; ayA = -2.0f*y; azA = -2.0f*z;
        x = g_cor[cb+3];  y = g_cor[cb+4];  z = g_cor[cb+5];
        c2B = x*x+y*y+z*z; axB = -2.0f*x; ayB = -2.0f*y; azB = -2.0f*z;
        x = g_cor[cb+6];  y = g_cor[cb+7];  z = g_cor[cb+8];
        c2C = x*x+y*y+z*z; axC = -2.0f*x; ayC = -2.0f*y; azC = -2.0f*z;
        x = g_cor[cb+9];  y = g_cor[cb+10]; z = g_cor[cb+11];
        c2D = x*x+y*y+z*z; axD = -2.0f*x; ayD = -2.0f*y; azD = -2.0f*z;
    }

    float dA0=1e30f,dA1=1e30f,dA2=1e30f; int iA0=0,iA1=0,iA2=0;
    float dB0=1e30f,dB1=1e30f,dB2=1e30f; int iB0=0,iB1=0,iB2=0;
    float dC0=1e30f,dC1=1e30f,dC2=1e30f; int iC0=0,iC1=0,iC2=0;
    float dD0=1e30f,dD1=1e30f,dD2=1e30f; int iD0=0,iD1=0,iD2=0;

    for (int t0 = 0; t0 < NN; t0 += 512) {
        __syncthreads();
        for (int i = tid; i < 512; i += 256) {
            int n = t0 + i;
            st[i] = make_float4(O[n*3], O[n*3+1], O[n*3+2], Q[n]);
        }
        __syncthreads();
        #pragma unroll 2
        for (int i = lane; i < 512; i += 32) {
            float4 pt = st[i];
            int n = t0 + i;
            float t;
            t = fmaf(axA, pt.x, pt.w + c2A); t = fmaf(ayA, pt.y, t); t = fmaf(azA, pt.z, t);
            if (t < dA2) {
                if (t < dA1) {
                    dA2 = dA1; iA2 = iA1;
                    if (t < dA0) { dA1 = dA0; iA1 = iA0; dA0 = t; iA0 = n; }
                    else         { dA1 = t;  iA1 = n; }
                } else { dA2 = t; iA2 = n; }
            }
            t = fmaf(axB, pt.x, pt.w + c2B); t = fmaf(ayB, pt.y, t); t = fmaf(azB, pt.z, t);
            if (t < dB2) {
                if (t < dB1) {
                    dB2 = dB1; iB2 = iB1;
                    if (t < dB0) { dB1 = dB0; iB1 = iB0; dB0 = t; iB0 = n; }
                    else         { dB1 = t;  iB1 = n; }
                } else { dB2 = t; iB2 = n; }
            }
            t = fmaf(axC, pt.x, pt.w + c2C); t = fmaf(ayC, pt.y, t); t = fmaf(azC, pt.z, t);
            if (t < dC2) {
                if (t < dC1) {
                    dC2 = dC1; iC2 = iC1;
                    if (t < dC0) { dC1 = dC0; iC1 = iC0; dC0 = t; iC0 = n; }
                    else         { dC1 = t;  iC1 = n; }
                } else { dC2 = t; iC2 = n; }
            }
            t = fmaf(axD, pt.x, pt.w + c2D); t = fmaf(ayD, pt.y, t); t = fmaf(azD, pt.z, t);
            if (t < dD2) {
                if (t < dD1) {
                    dD2 = dD1; iD2 = iD1;
                    if (t < dD0) { dD1 = dD0; iD1 = iD0; dD0 = t; iD0 = n; }
                    else         { dD1 = t;  iD1 = n; }
                } else { dD2 = t; iD2 = n; }
            }
        }
    }
    merge_write(dA0, dA1, dA2, iA0, iA1, iA2, mw[wid], mi[wid], lane, O, b, m0+0);
    merge_write(dB0, dB1, dB2, iB0, iB1, iB2, mw[wid], mi[wid], lane, O, b, m0+1);
    merge_write(dC0, dC1, dC2, iC0, iC1, iC2, mw[wid], mi[wid], lane, O, b, m0+2);
    merge_write(dD0, dD1, dD2, iD0, iD1, iD2, mw[wid], mi[wid], lane, O, b, m0+3);
}

// ---------------- combine v2: block = 32 corners, coalesced h1T row writes ----------------
__global__ void __launch_bounds__(256) combine_kernel(const float* __restrict__ w1,
                                                      const float* __restrict__ b1)
{
    __shared__ float wr0[128], wr1[128], wr2[128], sb[128];
    __shared__ float tr[128][33];
    int tid = threadIdx.x, lane = tid & 31, wid = tid >> 5;
    if (tid < 128) {
        const float* wrow = w1 + tid*131;
        wr0[tid] = wrow[0]; wr1[tid] = wrow[1]; wr2[tid] = wrow[2];
        sb[tid]  = b1[tid];
    }
    __syncthreads();
    int m0 = blockIdx.x*32;
    #pragma unroll 1
    for (int cc = 0; cc < 4; cc++) {
        int ml = wid*4 + cc;                         // 0..31 local corner
        int m  = m0 + ml;
        int b = m >> 13, mb = m & 8191;
        size_t base3 = ((size_t)b*M_TOT + mb)*3;
        int i0 = g_nni[base3+0], i1 = g_nni[base3+1], i2 = g_nni[base3+2];
        float w0 = g_nnw[base3+0], w1w = g_nnw[base3+1], w2w = g_nnw[base3+2];
        float rx = g_rel[(size_t)m*3+0], ry = g_rel[(size_t)m*3+1], rz = g_rel[(size_t)m*3+2];
        const float* G0 = g_G + ((size_t)b*NN + i0)*128;
        const float* G1 = g_G + ((size_t)b*NN + i1)*128;
        const float* G2 = g_G + ((size_t)b*NN + i2)*128;
        int c0 = lane*4;
        float4 a  = *(const float4*)(G0 + c0);
        float4 bq = *(const float4*)(G1 + c0);
        float4 cq = *(const float4*)(G2 + c0);
        float va[4] = {a.x,a.y,a.z,a.w};
        float vb[4] = {bq.x,bq.y,bq.z,bq.w};
        float vc[4] = {cq.x,cq.y,cq.z,cq.w};
        #pragma unroll
        for (int j = 0; j < 4; j++) {
            int o = c0 + j;
            float acc = w0*va[j] + w1w*vb[j] + w2w*vc[j];
            acc = fmaf(rx, wr0[o], acc);
            acc = fmaf(ry, wr1[o], acc);
            acc = fmaf(rz, wr2[o], acc);
            tr[o][ml] = fmaxf(acc + sb[o], 0.0f);
        }
    }
    __syncthreads();
    // write h1T rows: 128 rows x 32 floats, 128B per row, coalesced
    int c = tid >> 1, base = (tid & 1)*16;
    float* dst = &g_h1T[(size_t)c*MG + m0 + base];
    #pragma unroll
    for (int q = 0; q < 4; q++) {
        float4 v = {tr[c][base+q*4+0], tr[c][base+q*4+1], tr[c][base+q*4+2], tr[c][base+q*4+3]};
        *(float4*)(dst + q*4) = v;
    }
}

// ---------------- gemm2 (tf32 tensor-core) + fused relu + maxpool over 64 ----------------
__global__ void __launch_bounds__(256) gemm2_pool_kernel(const float* __restrict__ bias)
{
    __shared__ float As[2][16][132];     // [k][m], padded
    __shared__ float Bs[2][16][68];      // [k][o], padded
    __shared__ int spool[128];           // [2 pool-groups][64 o]
    int m0 = blockIdx.x*128, o0 = blockIdx.y*64;
    int tid = threadIdx.x, lane = tid & 31, wid = tid >> 5;
    int wm = wid >> 1, wn = wid & 1;
    int kr = tid >> 4, c16 = tid & 15;
    if (tid < 128) spool[tid] = 0;

    float acc[2][4][4] = {};

    {
        const float* ap = &g_h1T[(size_t)kr*MG + m0 + c16*8];
        float4 a0 = *(const float4*)ap;
        float4 a1 = *(const float4*)(ap + 4);
        float* d = &As[0][kr][c16*8];
        d[0]=tf32r(a0.x); d[1]=tf32r(a0.y); d[2]=tf32r(a0.z); d[3]=tf32r(a0.w);
        d[4]=tf32r(a1.x); d[5]=tf32r(a1.y); d[6]=tf32r(a1.z); d[7]=tf32r(a1.w);
        float4 bv = *(const float4*)&g_w2T[kr*256 + o0 + c16*4];
        float* e = &Bs[0][kr][c16*4];
        e[0]=tf32r(bv.x); e[1]=tf32r(bv.y); e[2]=tf32r(bv.z); e[3]=tf32r(bv.w);
    }
    __syncthreads();

    int buf = 0;
    int lk = lane & 3, lr = lane >> 2;
    #pragma unroll 1
    for (int kb = 0; kb < 8; kb++) {
        bool has = kb < 7;
        float4 na0, na1, nb;
        if (has) {
            int kk = (kb+1)*16 + kr;
            const float* ap = &g_h1T[(size_t)kk*MG + m0 + c16*8];
            na0 = *(const float4*)ap;
            na1 = *(const float4*)(ap + 4);
            nb  = *(const float4*)&g_w2T[kk*256 + o0 + c16*4];
        }
        #pragma unroll
        for (int ks = 0; ks < 2; ks++) {
            int klo = ks*8 + lk;
            uint32_t afr[2][4];
            #pragma unroll
            for (int mt = 0; mt < 2; mt++) {
                int mr = wm*32 + mt*16 + lr;
                afr[mt][0] = __float_as_uint(As[buf][klo  ][mr]);
                afr[mt][1] = __float_as_uint(As[buf][klo  ][mr+8]);
                afr[mt][2] = __float_as_uint(As[buf][klo+4][mr]);
                afr[mt][3] = __float_as_uint(As[buf][klo+4][mr+8]);
            }
            uint32_t bfr[4][2];
            #pragma unroll
            for (int nt = 0; nt < 4; nt++) {
                int nr = wn*32 + nt*8 + lr;
                bfr[nt][0] = __float_as_uint(Bs[buf][klo  ][nr]);
                bfr[nt][1] = __float_as_uint(Bs[buf][klo+4][nr]);
            }
            #pragma unroll
            for (int mt = 0; mt < 2; mt++)
                #pragma unroll
                for (int nt = 0; nt < 4; nt++)
                    mma_tf32(acc[mt][nt], afr[mt], bfr[nt]);
        }
        if (has) {
            int nbuf = buf^1;
            float* d = &As[nbuf][kr][c16*8];
            d[0]=tf32r(na0.x); d[1]=tf32r(na0.y); d[2]=tf32r(na0.z); d[3]=tf32r(na0.w);
            d[4]=tf32r(na1.x); d[5]=tf32r(na1.y); d[6]=tf32r(na1.z); d[7]=tf32r(na1.w);
            float* e = &Bs[nbuf][kr][c16*4];
            e[0]=tf32r(nb.x); e[1]=tf32r(nb.y); e[2]=tf32r(nb.z); e[3]=tf32r(nb.w);
            __syncthreads();
            buf = nbuf;
        }
    }

    int grp = wm >> 1;
    #pragma unroll
    for (int nt = 0; nt < 4; nt++) {
        int c0 = wn*32 + nt*8 + (lane & 3)*2;
        float b0v = bias[o0 + c0], b1v = bias[o0 + c0 + 1];
        float p0v = 0.0f, p1v = 0.0f;
        #pragma unroll
        for (int mt = 0; mt < 2; mt++) {
            p0v = fmaxf(p0v, acc[mt][nt][0] + b0v);
            p0v = fmaxf(p0v, acc[mt][nt][2] + b0v);
            p1v = fmaxf(p1v, acc[mt][nt][1] + b1v);
            p1v = fmaxf(p1v, acc[mt][nt][3] + b1v);
        }
        atomicMax(&spool[grp*64 + c0],     __float_as_int(p0v));
        atomicMax(&spool[grp*64 + c0 + 1], __float_as_int(p1v));
    }
    __syncthreads();
    if (tid < 128) {
        int g = tid >> 6, ol = tid & 63;
        int b  = m0 >> 13;
        int p0 = (m0 >> 6) & 127;
        g_pool[((size_t)b*256 + o0 + ol)*NPT + p0 + g] = __int_as_float(spool[g*64 + ol]);
    }
}

// ---------------- fused linear + train-mode BN + relu ----------------
__global__ void lin_bn_kernel(const float* __restrict__ W, const float* __restrict__ bias,
                              const float* __restrict__ gam, const float* __restrict__ bet,
                              int stage)
{
    int o = blockIdx.x, tid = threadIdx.x;            // 256 threads = (b,p)
    int b = tid >> 7, p = tid & 127;
    int K = stage ? 128 : 256;
    const float* X = stage ? g_z0 : g_pool;
    __shared__ float ws[256];
    if (tid < K) ws[tid] = W[o*K + tid];
    __syncthreads();
    const float* Xb = X + (size_t)b*K*NPT + p;
    float acc = bias[o];
    #pragma unroll 8
    for (int c = 0; c < K; c++) acc = fmaf(ws[c], Xb[(size_t)c*NPT], acc);
    __shared__ float red[256];
    red[tid] = acc; __syncthreads();
    #pragma unroll
    for (int s = 128; s > 0; s >>= 1) { if (tid < s) red[tid] += red[tid+s]; __syncthreads(); }
    float mean = red[0] * (1.0f/256.0f);
    __syncthreads();
    float d = acc - mean;
    red[tid] = d*d; __syncthreads();
    #pragma unroll
    for (int s = 128; s > 0; s >>= 1) { if (tid < s) red[tid] += red[tid+s]; __syncthreads(); }
    float var = red[0] * (1.0f/256.0f);
    float z = d * rsqrtf(var + 1e-5f) * gam[o] + bet[o];
    float* Y = stage ? g_z1 : g_z0;
    Y[((size_t)b*128 + o)*NPT + p] = fmaxf(z, 0.0f);
}

__global__ void final_kernel(const float* __restrict__ W, const float* __restrict__ bias,
                             float* __restrict__ out)
{
    int b = blockIdx.x, p = threadIdx.x;
    const float* Z = g_z1 + (size_t)b*128*NPT;
    float acc = bias[0];
    #pragma unroll 8
    for (int c = 0; c < 128; c++) acc = fmaf(W[c], Z[(size_t)c*NPT + p], acc);
    out[b*NPT + p] = acc;
}

// ---------------- launch ----------------
extern "C" void kernel_launch(void* const* d_in, const int* in_sizes, int n_in,
                              void* d_out, int out_size)
{
    const float* oxyz  = (const float*)d_in[0];
    const float* ofeat = (const float*)d_in[1];
    const float* cand  = (const float*)d_in[2];
    // d_in[3] = pred_cls (unused)
    const float* poff  = (const float*)d_in[4];
    const float* pacls = (const float*)d_in[5];
    const float* pares = (const float*)d_in[6];
    const float* w1    = (const float*)d_in[7];
    const float* b1    = (const float*)d_in[8];
    const float* w2    = (const float*)d_in[9];
    const float* b2    = (const float*)d_in[10];
    const float* wi0   = (const float*)d_in[11];
    const float* bi0   = (const float*)d_in[12];
    const float* gi0   = (const float*)d_in[13];
    const float* bei0  = (const float*)d_in[14];
    const float* wi1   = (const float*)d_in[15];
    const float* bi1   = (const float*)d_in[16];
    const float* gi1   = (const float*)d_in[17];
    const float* bei1  = (const float*)d_in[18];
    const float* wi2   = (const float*)d_in[19];
    const float* bi2   = (const float*)d_in[20];
    float* out = (float*)d_out;

    setup_a_kernel<<<128, 256>>>(cand, poff, pacls, pares, oxyz);   // #1
    setup_b_kernel<<<192, 256>>>(w1, w2);                           // #2
    gemmG_kernel<<<dim3(64, 2, 2), 256>>>(ofeat);                   // #3
    three_nn_kernel<<<512, 256>>>(oxyz);                            // #4 <- ncu lands here
    combine_kernel<<<512, 256>>>(w1, b1);                           // #5
    gemm2_pool_kernel<<<dim3(128, 4), 256>>>(b2);                   // #6
    lin_bn_kernel<<<128, 256>>>(wi0, bi0, gi0, bei0, 0);            // #7
    lin_bn_kernel<<<128, 256>>>(wi1, bi1, gi1, bei1, 1);            // #8
    final_kernel<<<2, 128>>>(wi2, bi2, out);                        // #9
}

// round 10
// speedup vs baseline: 1.1898x; 1.1898x over previous
#include <cuda_runtime.h>
#include <math.h>
#include <stdint.h>

#define BS2   2
#define NN    8192
#define NPT   128
#define CC    128
#define M_TOT 8192        // NPT*64 per batch
#define MG    16384       // total corners
#define FULLM 0xffffffffu

// ---------------- device scratch ----------------
static __device__ float g_p2[(size_t)BS2*NN];
static __device__ float g_rel[(size_t)MG*3];
static __device__ float g_cor[(size_t)MG*3];
static __device__ int   g_nni[(size_t)MG*3];
static __device__ float g_nnw[(size_t)MG*3];
static __device__ float g_w1T[128*128];                 // [k][o]
static __device__ float g_w2T[128*256];                 // [k][o]
static __device__ float g_G[(size_t)BS2*NN*128];        // [b][n][o] = W1f . f
static __device__ float g_h1T[(size_t)128*MG];          // [c][m]
static __device__ float g_pool[(size_t)BS2*256*NPT];    // [b][o][p]
static __device__ float g_z0[(size_t)BS2*128*NPT];
static __device__ float g_z1[(size_t)BS2*128*NPT];

__device__ __forceinline__ float tf32r(float x) {
    uint32_t u; asm("cvt.rna.tf32.f32 %0, %1;" : "=r"(u) : "f"(x));
    return __uint_as_float(u);
}

__device__ __forceinline__ void mma_tf32(float c[4], const uint32_t a[4], const uint32_t b[2]) {
    asm volatile(
        "mma.sync.aligned.m16n8k8.row.col.f32.tf32.tf32.f32 "
        "{%0,%1,%2,%3}, {%4,%5,%6,%7}, {%8,%9}, {%0,%1,%2,%3};\n"
        : "+f"(c[0]), "+f"(c[1]), "+f"(c[2]), "+f"(c[3])
        : "r"(a[0]), "r"(a[1]), "r"(a[2]), "r"(a[3]), "r"(b[0]), "r"(b[1]));
}

// ---------------- setup_a: decode + p2 ----------------
__global__ void setup_a_kernel(const float* __restrict__ cand,
                               const float* __restrict__ off,
                               const float* __restrict__ acls,
                               const float* __restrict__ ares,
                               const float* __restrict__ oxyz)
{
    int bx = blockIdx.x, tid = threadIdx.x;
    if (bx < 64) {
        int t = bx*256 + tid;                        // 16384 = b*8192 + p*64 + k
        int k  = t & 63;
        int bp = t >> 6;
        const float* a = acls + bp*12;
        float best = a[0]; int bi = 0;
        #pragma unroll
        for (int j = 1; j < 12; j++) { float v = a[j]; if (v > best) { best = v; bi = j; } }
        float res = ares[bp*12 + bi];
        const float PI_F = 3.14159265358979323846f;
        float ang = (float)bi * (float)(2.0*3.14159265358979323846/12.0) + res;
        float heading = (ang > PI_F) ? (ang - 2.0f*PI_F) : ang;
        float s, c; sincosf(heading, &s, &c);
        const float* o6 = off + bp*6;
        float cx = cand[bp*3+0] + o6[0];
        float cy = cand[bp*3+1] + o6[1];
        float cz = cand[bp*3+2] + o6[2];
        float lx = fmaxf(o6[3]*2.0f, 0.1f);
        float ly = fmaxf(o6[4]*2.0f, 0.1f);
        float lz = fmaxf(o6[5]*2.0f, 0.1f);
        float gv[4] = {-1.0f, -1.0f/3.0f, 1.0f/3.0f, 1.0f};
        float gx = gv[(k>>4)&3] * lx;
        float gy = gv[(k>>2)&3] * ly;
        float gz = gv[k&3]      * lz;
        float rx = gx*c - gy*s;
        float ry = gx*s + gy*c;
        float rz = gz;
        size_t b3 = (size_t)t*3;
        g_rel[b3+0] = rx; g_rel[b3+1] = ry; g_rel[b3+2] = rz;
        g_cor[b3+0] = rx + cx; g_cor[b3+1] = ry + cy; g_cor[b3+2] = rz + cz;
    } else {
        int t = (bx-64)*256 + tid;
        float x = oxyz[t*3], y = oxyz[t*3+1], z = oxyz[t*3+2];
        g_p2[t] = x*x + y*y + z*z;
    }
}

// ---------------- setup_b: transpose W1f / W2 ----------------
__global__ void setup_b_kernel(const float* __restrict__ w1, const float* __restrict__ w2)
{
    int bx = blockIdx.x, tid = threadIdx.x;
    if (bx < 64) {
        int t = bx*256 + tid;                        // 16384 = k*128+o
        int o = t & 127, k = t >> 7;
        g_w1T[t] = w1[o*131 + 3 + k];
    } else {
        int t = (bx-64)*256 + tid;                   // 32768 = k*256+o
        int o = t & 255, k = t >> 8;
        g_w2T[t] = w2[o*128 + k];
    }
}

// ---------------- gemm_G: 128n x 64o, BK=16, 8x4, double-buffered (proven) ----------------
__global__ void __launch_bounds__(256) gemmG_kernel(const float* __restrict__ feat)
{
    __shared__ float Ns[2][16][132];
    __shared__ float Os[2][16][64];
    int n0 = blockIdx.x*128, o0 = blockIdx.y*64, b = blockIdx.z;
    int tid = threadIdx.x;
    int kr  = tid >> 4;
    int nc  = (tid & 15)*8;
    int oc  = (tid & 15)*4;
    int tr  = (tid >> 4)*8;
    int tc  = (tid & 15)*4;
    const float* F = feat + (size_t)b*CC*NN;

    float acc[8][4] = {};
    float4 na0, na1, nb;
    na0 = *(const float4*)&F[(size_t)kr*NN + n0 + nc];
    na1 = *(const float4*)&F[(size_t)kr*NN + n0 + nc + 4];
    nb  = *(const float4*)&g_w1T[kr*128 + o0 + oc];
    *(float4*)&Ns[0][kr][nc]   = na0;
    *(float4*)&Ns[0][kr][nc+4] = na1;
    *(float4*)&Os[0][kr][oc]   = nb;
    __syncthreads();
    int buf = 0;
    #pragma unroll 1
    for (int kb = 0; kb < 8; kb++) {
        bool has = kb < 7;
        if (has) {
            int kk = (kb+1)*16 + kr;
            na0 = *(const float4*)&F[(size_t)kk*NN + n0 + nc];
            na1 = *(const float4*)&F[(size_t)kk*NN + n0 + nc + 4];
            nb  = *(const float4*)&g_w1T[kk*128 + o0 + oc];
        }
        #pragma unroll
        for (int k = 0; k < 16; k++) {
            float4 a0 = *(const float4*)&Ns[buf][k][tr];
            float4 a1 = *(const float4*)&Ns[buf][k][tr+4];
            float4 bq = *(const float4*)&Os[buf][k][tc];
            float ar[8] = {a0.x,a0.y,a0.z,a0.w,a1.x,a1.y,a1.z,a1.w};
            float br[4] = {bq.x,bq.y,bq.z,bq.w};
            #pragma unroll
            for (int i = 0; i < 8; i++)
                #pragma unroll
                for (int j = 0; j < 4; j++)
                    acc[i][j] = fmaf(ar[i], br[j], acc[i][j]);
        }
        if (has) {
            int nbuf = buf^1;
            *(float4*)&Ns[nbuf][kr][nc]   = na0;
            *(float4*)&Ns[nbuf][kr][nc+4] = na1;
            *(float4*)&Os[nbuf][kr][oc]   = nb;
            __syncthreads();
            buf = nbuf;
        }
    }
    float* Gp = g_G + ((size_t)b*NN + n0 + tr)*128 + o0 + tc;
    #pragma unroll
    for (int i = 0; i < 8; i++) {
        float4 v = {acc[i][0], acc[i][1], acc[i][2], acc[i][3]};
        *(float4*)(Gp + (size_t)i*128) = v;
    }
}

// warp-uniform branchless insert of (tt, nn_) into sorted top-3
#define INSERT3(tt, nn_, d0, i0, d1, i1, d2, i2)               \
    do {                                                        \
        bool q2 = (tt) < (d2), q1 = (tt) < (d1), q0 = (tt) < (d0); \
        (d2) = q1 ? (d1) : (q2 ? (tt) : (d2));                  \
        (i2) = q1 ? (i1) : (q2 ? (nn_) : (i2));                 \
        (d1) = q0 ? (d0) : (q1 ? (tt) : (d1));                  \
        (i1) = q0 ? (i0) : (q1 ? (nn_) : (i1));                 \
        (d0) = q0 ? (tt) : (d0);                                \
        (i0) = q0 ? (nn_) : (i0);                               \
    } while (0)

// write one corner's result (values are warp-uniform; lane 0 writes)
__device__ __forceinline__ void write_top3(int lane, const float* __restrict__ O,
                                           int b, int m, int i0, int i1, int i2)
{
    if (lane == 0) {
        size_t cb = ((size_t)b*M_TOT + m)*3;
        float cx = g_cor[cb+0], cy = g_cor[cb+1], cz = g_cor[cb+2];
        int win[3] = {i0, i1, i2};
        float w[3], ssum = 0.0f;
        #pragma unroll
        for (int r = 0; r < 3; r++) {
            const float* P = O + (size_t)win[r]*3;
            float dx = P[0]-cx, dy = P[1]-cy, dz = P[2]-cz;
            float d = sqrtf(dx*dx + dy*dy + dz*dz);
            w[r] = 1.0f / (d + 1e-8f);
            ssum += w[r];
        }
        float inv = 1.0f/ssum;
        #pragma unroll
        for (int r = 0; r < 3; r++) { g_nni[cb+r] = win[r]; g_nnw[cb+r] = w[r]*inv; }
    }
}

// ---------------- three_nn: warp handles 4 corners, warp-shared top-3, vote-gated ----------------
__global__ void __launch_bounds__(256) three_nn_kernel(const float* __restrict__ oxyz)
{
    __shared__ float4 st[512];
    int tid = threadIdx.x, lane = tid & 31, wid = tid >> 5;
    int gw = blockIdx.x*8 + wid;                     // 0..4095
    int b  = gw >> 11;                               // 2048 warps per batch
    int m0 = (gw & 2047) * 4;
    const float* O = oxyz + (size_t)b*NN*3;
    const float* Q = g_p2 + (size_t)b*NN;

    size_t cb = ((size_t)b*M_TOT + m0)*3;
    float c2A, axA, ayA, azA, c2B, axB, ayB, azB;
    float c2C, axC, ayC, azC, c2D, axD, ayD, azD;
    {
        float x, y, z;
        x = g_cor[cb+0];  y = g_cor[cb+1];  z = g_cor[cb+2];
        c2A = x*x+y*y+z*z; axA = -2.0f*x; ayA = -2.0f*y; azA = -2.0f*z;
        x = g_cor[cb+3];  y = g_cor[cb+4];  z = g_cor[cb+5];
        c2B = x*x+y*y+z*z; axB = -2.0f*x; ayB = -2.0f*y; azB = -2.0f*z;
        x = g_cor[cb+6];  y = g_cor[cb+7];  z = g_cor[cb+8];
        c2C = x*x+y*y+z*z; axC = -2.0f*x; ayC = -2.0f*y; azC = -2.0f*z;
        x = g_cor[cb+9];  y = g_cor[cb+10]; z = g_cor[cb+11];
        c2D = x*x+y*y+z*z; axD = -2.0f*x; ayD = -2.0f*y; azD = -2.0f*z;
    }

    // warp-uniform (replicated) top-3 per corner
    float dA0=1e30f,dA1=1e30f,dA2=1e30f; int iA0=0,iA1=0,iA2=0;
    float dB0=1e30f,dB1=1e30f,dB2=1e30f; int iB0=0,iB1=0,iB2=0;
    float dC0=1e30f,dC1=1e30f,dC2=1e30f; int iC0=0,iC1=0,iC2=0;
    float dD0=1e30f,dD1=1e30f,dD2=1e30f; int iD0=0,iD1=0,iD2=0;

    for (int t0 = 0; t0 < NN; t0 += 512) {
        __syncthreads();
        for (int i = tid; i < 512; i += 256) {
            int n = t0 + i;
            st[i] = make_float4(O[n*3], O[n*3+1], O[n*3+2], Q[n]);
        }
        __syncthreads();
        #pragma unroll 2
        for (int j = 0; j < 16; j++) {
            float4 pt = st[j*32 + lane];
            int nbase = t0 + j*32;
            float tA = fmaf(axA, pt.x, pt.w + c2A); tA = fmaf(ayA, pt.y, tA); tA = fmaf(azA, pt.z, tA);
            float tB = fmaf(axB, pt.x, pt.w + c2B); tB = fmaf(ayB, pt.y, tB); tB = fmaf(azB, pt.z, tB);
            float tC = fmaf(axC, pt.x, pt.w + c2C); tC = fmaf(ayC, pt.y, tC); tC = fmaf(azC, pt.z, tC);
            float tD = fmaf(axD, pt.x, pt.w + c2D); tD = fmaf(ayD, pt.y, tD); tD = fmaf(azD, pt.z, tD);
            bool cA = tA < dA2, cB = tB < dB2, cC = tC < dC2, cD = tD < dD2;
            if (__any_sync(FULLM, cA | cB | cC | cD)) {
                unsigned bal;
                bal = __ballot_sync(FULLM, cA);
                while (bal) {
                    int s = __ffs(bal) - 1; bal &= bal - 1;
                    float tt = __shfl_sync(FULLM, tA, s); int nn_ = nbase + s;
                    INSERT3(tt, nn_, dA0, iA0, dA1, iA1, dA2, iA2);
                }
                bal = __ballot_sync(FULLM, cB);
                while (bal) {
                    int s = __ffs(bal) - 1; bal &= bal - 1;
                    float tt = __shfl_sync(FULLM, tB, s); int nn_ = nbase + s;
                    INSERT3(tt, nn_, dB0, iB0, dB1, iB1, dB2, iB2);
                }
                bal = __ballot_sync(FULLM, cC);
                while (bal) {
                    int s = __ffs(bal) - 1; bal &= bal - 1;
                    float tt = __shfl_sync(FULLM, tC, s); int nn_ = nbase + s;
                    INSERT3(tt, nn_, dC0, iC0, dC1, iC1, dC2, iC2);
                }
                bal = __ballot_sync(FULLM, cD);
                while (bal) {
                    int s = __ffs(bal) - 1; bal &= bal - 1;
                    float tt = __shfl_sync(FULLM, tD, s); int nn_ = nbase + s;
                    INSERT3(tt, nn_, dD0, iD0, dD1, iD1, dD2, iD2);
                }
            }
        }
    }
    write_top3(lane, O, b, m0+0, iA0, iA1, iA2);
    write_top3(lane, O, b, m0+1, iB0, iB1, iB2);
    write_top3(lane, O, b, m0+2, iC0, iC1, iC2);
    write_top3(lane, O, b, m0+3, iD0, iD1, iD2);
}

// ---------------- combine v2: block = 32 corners, coalesced h1T row writes ----------------
__global__ void __launch_bounds__(256) combine_kernel(const float* __restrict__ w1,
                                                      const float* __restrict__ b1)
{
    __shared__ float wr0[128], wr1[128], wr2[128], sb[128];
    __shared__ float tr[128][33];
    int tid = threadIdx.x, lane = tid & 31, wid = tid >> 5;
    if (tid < 128) {
        const float* wrow = w1 + tid*131;
        wr0[tid] = wrow[0]; wr1[tid] = wrow[1]; wr2[tid] = wrow[2];
        sb[tid]  = b1[tid];
    }
    __syncthreads();
    int m0 = blockIdx.x*32;
    #pragma unroll 1
    for (int cc = 0; cc < 4; cc++) {
        int ml = wid*4 + cc;                         // 0..31 local corner
        int m  = m0 + ml;
        int b = m >> 13, mb = m & 8191;
        size_t base3 = ((size_t)b*M_TOT + mb)*3;
        int i0 = g_nni[base3+0], i1 = g_nni[base3+1], i2 = g_nni[base3+2];
        float w0 = g_nnw[base3+0], w1w = g_nnw[base3+1], w2w = g_nnw[base3+2];
        float rx = g_rel[(size_t)m*3+0], ry = g_rel[(size_t)m*3+1], rz = g_rel[(size_t)m*3+2];
        const float* G0 = g_G + ((size_t)b*NN + i0)*128;
        const float* G1 = g_G + ((size_t)b*NN + i1)*128;
        const float* G2 = g_G + ((size_t)b*NN + i2)*128;
        int c0 = lane*4;
        float4 a  = *(const float4*)(G0 + c0);
        float4 bq = *(const float4*)(G1 + c0);
        float4 cq = *(const float4*)(G2 + c0);
        float va[4] = {a.x,a.y,a.z,a.w};
        float vb[4] = {bq.x,bq.y,bq.z,bq.w};
        float vc[4] = {cq.x,cq.y,cq.z,cq.w};
        #pragma unroll
        for (int j = 0; j < 4; j++) {
            int o = c0 + j;
            float acc = w0*va[j] + w1w*vb[j] + w2w*vc[j];
            acc = fmaf(rx, wr0[o], acc);
            acc = fmaf(ry, wr1[o], acc);
            acc = fmaf(rz, wr2[o], acc);
            tr[o][ml] = fmaxf(acc + sb[o], 0.0f);
        }
    }
    __syncthreads();
    // write h1T rows: 128 rows x 32 floats, 128B per row, coalesced
    int c = tid >> 1, base = (tid & 1)*16;
    float* dst = &g_h1T[(size_t)c*MG + m0 + base];
    #pragma unroll
    for (int q = 0; q < 4; q++) {
        float4 v = {tr[c][base+q*4+0], tr[c][base+q*4+1], tr[c][base+q*4+2], tr[c][base+q*4+3]};
        *(float4*)(dst + q*4) = v;
    }
}

// ---------------- gemm2 (tf32 tensor-core) + fused relu + maxpool over 64 ----------------
__global__ void __launch_bounds__(256) gemm2_pool_kernel(const float* __restrict__ bias)
{
    __shared__ float As[2][16][132];     // [k][m], padded
    __shared__ float Bs[2][16][68];      // [k][o], padded
    __shared__ int spool[128];           // [2 pool-groups][64 o]
    int m0 = blockIdx.x*128, o0 = blockIdx.y*64;
    int tid = threadIdx.x, lane = tid & 31, wid = tid >> 5;
    int wm = wid >> 1, wn = wid & 1;
    int kr = tid >> 4, c16 = tid & 15;
    if (tid < 128) spool[tid] = 0;

    float acc[2][4][4] = {};

    {
        const float* ap = &g_h1T[(size_t)kr*MG + m0 + c16*8];
        float4 a0 = *(const float4*)ap;
        float4 a1 = *(const float4*)(ap + 4);
        float* d = &As[0][kr][c16*8];
        d[0]=tf32r(a0.x); d[1]=tf32r(a0.y); d[2]=tf32r(a0.z); d[3]=tf32r(a0.w);
        d[4]=tf32r(a1.x); d[5]=tf32r(a1.y); d[6]=tf32r(a1.z); d[7]=tf32r(a1.w);
        float4 bv = *(const float4*)&g_w2T[kr*256 + o0 + c16*4];
        float* e = &Bs[0][kr][c16*4];
        e[0]=tf32r(bv.x); e[1]=tf32r(bv.y); e[2]=tf32r(bv.z); e[3]=tf32r(bv.w);
    }
    __syncthreads();

    int buf = 0;
    int lk = lane & 3, lr = lane >> 2;
    #pragma unroll 1
    for (int kb = 0; kb < 8; kb++) {
        bool has = kb < 7;
        float4 na0, na1, nb;
        if (has) {
            int kk = (kb+1)*16 + kr;
            const float* ap = &g_h1T[(size_t)kk*MG + m0 + c16*8];
            na0 = *(const float4*)ap;
            na1 = *(const float4*)(ap + 4);
            nb  = *(const float4*)&g_w2T[kk*256 + o0 + c16*4];
        }
        #pragma unroll
        for (int ks = 0; ks < 2; ks++) {
            int klo = ks*8 + lk;
            uint32_t afr[2][4];
            #pragma unroll
            for (int mt = 0; mt < 2; mt++) {
                int mr = wm*32 + mt*16 + lr;
                afr[mt][0] = __float_as_uint(As[buf][klo  ][mr]);
                afr[mt][1] = __float_as_uint(As[buf][klo  ][mr+8]);
                afr[mt][2] = __float_as_uint(As[buf][klo+4][mr]);
                afr[mt][3] = __float_as_uint(As[buf][klo+4][mr+8]);
            }
            uint32_t bfr[4][2];
            #pragma unroll
            for (int nt = 0; nt < 4; nt++) {
                int nr = wn*32 + nt*8 + lr;
                bfr[nt][0] = __float_as_uint(Bs[buf][klo  ][nr]);
                bfr[nt][1] = __float_as_uint(Bs[buf][klo+4][nr]);
            }
            #pragma unroll
            for (int mt = 0; mt < 2; mt++)
                #pragma unroll
                for (int nt = 0; nt < 4; nt++)
                    mma_tf32(acc[mt][nt], afr[mt], bfr[nt]);
        }
        if (has) {
            int nbuf = buf^1;
            float* d = &As[nbuf][kr][c16*8];
            d[0]=tf32r(na0.x); d[1]=tf32r(na0.y); d[2]=tf32r(na0.z); d[3]=tf32r(na0.w);
            d[4]=tf32r(na1.x); d[5]=tf32r(na1.y); d[6]=tf32r(na1.z); d[7]=tf32r(na1.w);
            float* e = &Bs[nbuf][kr][c16*4];
            e[0]=tf32r(nb.x); e[1]=tf32r(nb.y); e[2]=tf32r(nb.z); e[3]=tf32r(nb.w);
            __syncthreads();
            buf = nbuf;
        }
    }

    int grp = wm >> 1;
    #pragma unroll
    for (int nt = 0; nt < 4; nt++) {
        int c0 = wn*32 + nt*8 + (lane & 3)*2;
        float b0v = bias[o0 + c0], b1v = bias[o0 + c0 + 1];
        float p0v = 0.0f, p1v = 0.0f;
        #pragma unroll
        for (int mt = 0; mt < 2; mt++) {
            p0v = fmaxf(p0v, acc[mt][nt][0] + b0v);
            p0v = fmaxf(p0v, acc[mt][nt][2] + b0v);
            p1v = fmaxf(p1v, acc[mt][nt][1] + b1v);
            p1v = fmaxf(p1v, acc[mt][nt][3] + b1v);
        }
        atomicMax(&spool[grp*64 + c0],     __float_as_int(p0v));
        atomicMax(&spool[grp*64 + c0 + 1], __float_as_int(p1v));
    }
    __syncthreads();
    if (tid < 128) {
        int g = tid >> 6, ol = tid & 63;
        int b  = m0 >> 13;
        int p0 = (m0 >> 6) & 127;
        g_pool[((size_t)b*256 + o0 + ol)*NPT + p0 + g] = __int_as_float(spool[g*64 + ol]);
    }
}

// ---------------- fused linear + train-mode BN + relu ----------------
__global__ void lin_bn_kernel(const float* __restrict__ W, const float* __restrict__ bias,
                              const float* __restrict__ gam, const float* __restrict__ bet,
                              int stage)
{
    int o = blockIdx.x, tid = threadIdx.x;            // 256 threads = (b,p)
    int b = tid >> 7, p = tid & 127;
    int K = stage ? 128 : 256;
    const float* X = stage ? g_z0 : g_pool;
    __shared__ float ws[256];
    if (tid < K) ws[tid] = W[o*K + tid];
    __syncthreads();
    const float* Xb = X + (size_t)b*K*NPT + p;
    float acc = bias[o];
    #pragma unroll 8
    for (int c = 0; c < K; c++) acc = fmaf(ws[c], Xb[(size_t)c*NPT], acc);
    __shared__ float red[256];
    red[tid] = acc; __syncthreads();
    #pragma unroll
    for (int s = 128; s > 0; s >>= 1) { if (tid < s) red[tid] += red[tid+s]; __syncthreads(); }
    float mean = red[0] * (1.0f/256.0f);
    __syncthreads();
    float d = acc - mean;
    red[tid] = d*d; __syncthreads();
    #pragma unroll
    for (int s = 128; s > 0; s >>= 1) { if (tid < s) red[tid] += red[tid+s]; __syncthreads(); }
    float var = red[0] * (1.0f/256.0f);
    float z = d * rsqrtf(var + 1e-5f) * gam[o] + bet[o];
    float* Y = stage ? g_z1 : g_z0;
    Y[((size_t)b*128 + o)*NPT + p] = fmaxf(z, 0.0f);
}

__global__ void final_kernel(const float* __restrict__ W, const float* __restrict__ bias,
                             float* __restrict__ out)
{
    int b = blockIdx.x, p = threadIdx.x;
    const float* Z = g_z1 + (size_t)b*128*NPT;
    float acc = bias[0];
    #pragma unroll 8
    for (int c = 0; c < 128; c++) acc = fmaf(W[c], Z[(size_t)c*NPT + p], acc);
    out[b*NPT + p] = acc;
}

// ---------------- launch ----------------
extern "C" void kernel_launch(void* const* d_in, const int* in_sizes, int n_in,
                              void* d_out, int out_size)
{
    const float* oxyz  = (const float*)d_in[0];
    const float* ofeat = (const float*)d_in[1];
    const float* cand  = (const float*)d_in[2];
    // d_in[3] = pred_cls (unused)
    const float* poff  = (const float*)d_in[4];
    const float* pacls = (const float*)d_in[5];
    const float* pares = (const float*)d_in[6];
    const float* w1    = (const float*)d_in[7];
    const float* b1    = (const float*)d_in[8];
    const float* w2    = (const float*)d_in[9];
    const float* b2    = (const float*)d_in[10];
    const float* wi0   = (const float*)d_in[11];
    const float* bi0   = (const float*)d_in[12];
    const float* gi0   = (const float*)d_in[13];
    const float* bei0  = (const float*)d_in[14];
    const float* wi1   = (const float*)d_in[15];
    const float* bi1   = (const float*)d_in[16];
    const float* gi1   = (const float*)d_in[17];
    const float* bei1  = (const float*)d_in[18];
    const float* wi2   = (const float*)d_in[19];
    const float* bi2   = (const float*)d_in[20];
    float* out = (float*)d_out;

    setup_a_kernel<<<128, 256>>>(cand, poff, pacls, pares, oxyz);   // #1
    setup_b_kernel<<<192, 256>>>(w1, w2);                           // #2
    gemmG_kernel<<<dim3(64, 2, 2), 256>>>(ofeat);                   // #3
    three_nn_kernel<<<512, 256>>>(oxyz);                            // #4 <- ncu lands here
    combine_kernel<<<512, 256>>>(w1, b1);                           // #5
    gemm2_pool_kernel<<<dim3(128, 4), 256>>>(b2);                   // #6
    lin_bn_kernel<<<128, 256>>>(wi0, bi0, gi0, bei0, 0);            // #7
    lin_bn_kernel<<<128, 256>>>(wi1, bi1, gi1, bei1, 1);            // #8
    final_kernel<<<2, 128>>>(wi2, bi2, out);                        // #9
}